// round 9
// baseline (speedup 1.0000x reference)
#include <cuda_runtime.h>
#include <math_constants.h>

// ---------------------------------------------------------------------------
// IttiKochSaliency, x[8,3,512,512] -> out[8,512,512]  —  ONE persistent kernel
//
// 148 blocks x 1024 threads, 1 block/SM guaranteed (120KB smem + lb(1024,1)),
// software sense-reversing global barrier between phases:
//   P1: x -> L1 (256^2), separable 6-tap stride-2 reflect (3072 tiles, two
//       512-thread halves per block)
//   P2: L1 -> L2 + diff0 + stats (768 tiles)
//   P3: L2 -> L3 + diff1 + stats (192 tiles)
//   P4: blocks 0..7: per-batch tail (pyramid 64->2, diffs i=2..6, stats,
//       quad-dup comb maps); blocks 8..147: comb strips for i=0,1
//   P5: final 7-level bilinear gather, 7 LDG.128/px (2048 row-pair items)
// 4 global barriers (even -> barrier state self-resets for graph replays).
// ---------------------------------------------------------------------------

__device__ float    g_pyr[2064384];
__device__ float    g_d[1966080];
__device__ float4   g_q[699008];
__device__ unsigned g_dmn[168], g_dmx[168];
__device__ float    g_tsum[168];
__device__ unsigned g_cnt = 0u;
__device__ volatile unsigned g_sense = 0u;

__constant__ int c_off[3] = {0, 1572864, 1966080};
__constant__ int co2[7]  = {0, 524288, 655360, 688128, 696320, 698368, 698880};

#define NBLK 148

__device__ __forceinline__ int refl(int t, int n) {
    return t < 0 ? -t : (t >= n ? 2 * n - 2 - t : t);
}
__device__ __forceinline__ float calc_scale(int sidx, int i, float* mn_out) {
    float mn = __uint_as_float(g_dmn[sidx]);
    float mx = __uint_as_float(g_dmx[sidx]);
    float inv = 1.f / (mx - mn);
    int n = (16 >> i) - 1;
    float lm = (n > 0) ? (g_tsum[sidx] / (float)(n * n) - mn) * inv : 0.f;
    float om = 1.f - lm;
    *mn_out = mn;
    return om * om * inv * (1.f / 3.f);
}

#define W0 0.03125f
#define W1 0.15625f
#define W2 0.3125f

// ---- separable pyrdown tile (32x16 out), 512-thread half, with trailing bar
__device__ __forceinline__ void pyr_tile(int tl, int valid, int HI,
                                         const float* __restrict__ in,
                                         float* __restrict__ outp,
                                         int ox0, int oy0,
                                         float* s_in, float* s_h, float* sout) {
    const int HO = HI >> 1;
    const int iy0 = 2 * oy0 - 2, ix0 = 2 * ox0 - 2;
    if (valid) {
        for (int idx = tl; idx < 36 * 34; idx += 512) {
            int r = idx / 34, c2 = idx - r * 34;
            int gy = refl(iy0 + r, HI);
            int ix = ix0 + 2 * c2;
            float v0, v1;
            if (ix >= 0 && ix + 2 <= HI) {
                float2 p = *(const float2*)(in + gy * HI + ix);
                v0 = p.x; v1 = p.y;
            } else {
                v0 = in[gy * HI + refl(ix, HI)];
                v1 = in[gy * HI + refl(ix + 1, HI)];
            }
            s_in[r * 68 + 2 * c2] = v0;
            s_in[r * 68 + 2 * c2 + 1] = v1;
        }
    }
    __syncthreads();
    if (valid) {
        for (int idx = tl; idx < 36 * 32; idx += 512) {
            int r = idx >> 5, c = idx & 31;
            const float* p = s_in + r * 68 + 2 * c;
            s_h[idx] = W0 * (p[0] + p[5]) + W1 * (p[1] + p[4]) + W2 * (p[2] + p[3]);
        }
    }
    __syncthreads();
    if (valid) {
        const int tx = tl & 31, ty = tl >> 5;
        const float* q = s_h + 2 * ty * 32 + tx;
        float acc = W0 * (q[0] + q[160]) + W1 * (q[32] + q[128]) + W2 * (q[64] + q[96]);
        outp[(oy0 + ty) * HO + ox0 + tx] = acc;
        if (sout) sout[ty * 32 + tx] = acc;
    }
    __syncthreads();
}

// ---- pyrdown + fused diff (I = 0 or 1), 512-thread half ----------------------
__device__ __forceinline__ void pd_tile(int tl, int valid, int I, int bc,
                                        int tilex, int tiley,
                                        float* s_in, float* s_h, float* sout,
                                        unsigned* stat) {
    const int HI = 256 >> I;
    const int ox0 = tilex * 32, oy0 = tiley * 16;
    if (valid) {
        if (tl == 0) { stat[0] = 0xFFFFFFFFu; stat[1] = 0u; }
        if (tl < 8) stat[2 + tl] = 0u;
    }
    const float* in = g_pyr + c_off[I] + (size_t)bc * HI * HI;
    float* outp = g_pyr + c_off[I + 1] + (size_t)bc * (HI >> 1) * (HI >> 1);
    pyr_tile(tl, valid, HI, in, outp, ox0, oy0, s_in, s_h, sout);
    if (valid) {
        const int p4 = tl * 4;
        const int ly = p4 >> 6, lx = p4 & 63;
        const float* fr = s_in + (ly + 2) * 68 + lx + 2;
        const float c0 = sout[(ly >> 1) * 32 + (lx >> 1)];
        const float c1 = sout[(ly >> 1) * 32 + (lx >> 1) + 1];
        float d0 = fabsf(fr[0] - c0), d1 = fabsf(fr[1] - c0);
        float d2 = fabsf(fr[2] - c1), d3 = fabsf(fr[3] - c1);
        float* gd = g_d + (I ? 1572864 : 0) + (size_t)bc * HI * HI;
        *(float4*)(gd + (2 * oy0 + ly) * HI + 2 * ox0 + lx) = make_float4(d0, d1, d2, d3);
        float mx4 = fmaxf(fmaxf(d0, d1), fmaxf(d2, d3));
        float mn4 = fminf(fminf(d0, d1), fminf(d2, d3));
        float tm = mx4;
        tm = fmaxf(tm, __shfl_xor_sync(~0u, tm, 1, 4));
        tm = fmaxf(tm, __shfl_xor_sync(~0u, tm, 2, 4));
        if ((tl & 3) == 0)
            atomicMax(&stat[2 + (ly >> 4) * 4 + (lx >> 4)], __float_as_uint(tm));
        for (int o = 16; o; o >>= 1) {
            mx4 = fmaxf(mx4, __shfl_xor_sync(~0u, mx4, o));
            mn4 = fminf(mn4, __shfl_xor_sync(~0u, mn4, o));
        }
        if ((tl & 31) == 0) {
            atomicMax(&stat[1], __float_as_uint(mx4));
            atomicMin(&stat[0], __float_as_uint(mn4));
        }
    }
    __syncthreads();
    if (valid) {
        const int sidx = bc * 7 + I;
        if (tl == 0) { atomicMin(&g_dmn[sidx], stat[0]); atomicMax(&g_dmx[sidx], stat[1]); }
        if (tl < 8) {
            const int NT = (16 >> I) - 1;
            int gtc = 4 * tilex + (tl & 3);
            int gtr = 2 * tiley + (tl >> 2);
            if (gtc < NT && gtr < NT)
                atomicAdd(&g_tsum[sidx], __uint_as_float(stat[2 + tl]));
        }
    }
    __syncthreads();
}

// ---- one tail stage, 3 channels in parallel, 1024 threads --------------------
template <int LGF>
__device__ __forceinline__ void tail_stage(int t, int b, float* Fb, int FS,
                                           float* Cb, int CS, float* H,
                                           unsigned* t_mn, unsigned* t_mx,
                                           unsigned* t_tile, float* t_s) {
    constexpr int HF = 1 << LGF, HC = HF >> 1, I = 8 - LGF;
    for (int idx = t; idx < 3 * HF * HC; idx += 1024) {
        int c = idx / (HF * HC);
        int rem = idx - c * (HF * HC);
        int r = rem >> (LGF - 1);
        const float* row = Fb + c * FS + (r << LGF);
        int c0 = 2 * (rem & (HC - 1));
        H[c * 2048 + rem] = W0 * (row[refl(c0 - 2, HF)] + row[refl(c0 + 3, HF)])
                          + W1 * (row[refl(c0 - 1, HF)] + row[refl(c0 + 2, HF)])
                          + W2 * (row[c0] + row[c0 + 1]);
    }
    __syncthreads();
    for (int idx = t; idx < 3 * HC * HC; idx += 1024) {
        int c = idx / (HC * HC);
        int rem = idx - c * (HC * HC);
        int oy = rem >> (LGF - 1), ox = rem & (HC - 1);
        const float* hb = H + c * 2048;
        int r0 = 2 * oy;
        float cv = W0 * (hb[(refl(r0 - 2, HF) << (LGF - 1)) + ox] +
                         hb[(refl(r0 + 3, HF) << (LGF - 1)) + ox])
                 + W1 * (hb[(refl(r0 - 1, HF) << (LGF - 1)) + ox] +
                         hb[(refl(r0 + 2, HF) << (LGF - 1)) + ox])
                 + W2 * (hb[(r0 << (LGF - 1)) + ox] + hb[((r0 + 1) << (LGF - 1)) + ox]);
        Cb[c * CS + rem] = cv;
        float* A = Fb + c * FS;
        int f0 = (oy << (LGF + 1)) + 2 * ox;
        float d00 = fabsf(A[f0] - cv),      d01 = fabsf(A[f0 + 1] - cv);
        float d10 = fabsf(A[f0 + HF] - cv), d11 = fabsf(A[f0 + HF + 1] - cv);
        A[f0] = d00; A[f0 + 1] = d01; A[f0 + HF] = d10; A[f0 + HF + 1] = d11;
        float mx4 = fmaxf(fmaxf(d00, d01), fmaxf(d10, d11));
        float mn4 = fminf(fminf(d00, d01), fminf(d10, d11));
        if (LGF >= 4) {
            float a = mx4, n2 = mn4;
            for (int o = 16; o; o >>= 1) {
                a = fmaxf(a, __shfl_xor_sync(~0u, a, o));
                n2 = fminf(n2, __shfl_xor_sync(~0u, n2, o));
            }
            if ((t & 31) == 0) {
                atomicMax(&t_mx[c], __float_as_uint(a));
                atomicMin(&t_mn[c], __float_as_uint(n2));
            }
        } else {
            atomicMax(&t_mx[c], __float_as_uint(mx4));
            atomicMin(&t_mn[c], __float_as_uint(mn4));
        }
        if (LGF == 6)
            atomicMax(&t_tile[c * 16 + (oy >> 3) * 4 + (ox >> 3)], __float_as_uint(mx4));
        else if (LGF == 5) {
            if (oy < 8 && ox < 8) atomicMax(&t_tile[c * 16], __float_as_uint(mx4));
        }
    }
    __syncthreads();
    if (t < 3) {
        float mn = __uint_as_float(t_mn[t]), mx = __uint_as_float(t_mx[t]);
        float ts = 0.f;
        if (LGF == 6) {
            for (int k = 0; k < 3; k++)
                for (int j = 0; j < 3; j++) ts += __uint_as_float(t_tile[t * 16 + k * 4 + j]);
        } else if (LGF == 5) ts = __uint_as_float(t_tile[t * 16]);
        int sidx = (b * 3 + t) * 7 + I;
        g_dmn[sidx] = __float_as_uint(mn);
        g_dmx[sidx] = __float_as_uint(mx);
        g_tsum[sidx] = ts;
        float inv = 1.f / (mx - mn);
        constexpr int NTT = (LGF == 6) ? 3 : (LGF == 5 ? 1 : 0);
        float lm = (NTT > 0) ? (ts / (float)(NTT * NTT) - mn) * inv : 0.f;
        float om = 1.f - lm;
        t_s[t] = om * om * inv * (1.f / 3.f);
    }
    __syncthreads();
    // comb (reads t_s, F) + reset of stats for next stage (disjoint addresses)
    if (t >= 512 && t < 560) t_tile[t - 512] = 0u;
    if (t >= 560 && t < 563) { t_mn[t - 560] = 0xFFFFFFFFu; t_mx[t - 560] = 0u; }
    for (int idx = t; idx < HF * HF; idx += 1024) {
        int y = idx >> LGF, x = idx & (HF - 1);
        int x1 = min(x + 1, HF - 1), y1 = min(y + 1, HF - 1);
        float4 q = make_float4(0.f, 0.f, 0.f, 0.f);
#pragma unroll
        for (int c = 0; c < 3; c++) {
            const float* A = Fb + c * FS;
            float s = t_s[c];
            q.x = fmaf(A[(y << LGF) + x], s, q.x);
            q.y = fmaf(A[(y << LGF) + x1], s, q.y);
            q.z = fmaf(A[(y1 << LGF) + x], s, q.z);
            q.w = fmaf(A[(y1 << LGF) + x1], s, q.w);
        }
        g_q[co2[I] + b * HF * HF + idx] = q;
    }
    __syncthreads();
}

// ---- comb strip for i=0,1 (full-width 16-row strip), 1024 threads -------------
__device__ __forceinline__ void comb_strip(int t, int k, float* sm, float* scs) {
    __syncthreads();   // protect previous item's smem reads
    int i, b, y0, lg;
    if (k < 128) { i = 0; b = k >> 4; y0 = (k & 15) * 16; lg = 8; }
    else { int r = k - 128; i = 1; b = r >> 3; y0 = (r & 7) * 16; lg = 7; }
    const int h = 1 << lg, S = h + 2, W = h + 1;
    float* sv = sm;
    if (t < 3) { float mn; scs[t] = calc_scale((b * 3 + t) * 7 + i, i, &mn); }
    __syncthreads();
    const float* db = g_d + (i ? 1572864 : 0) + (size_t)(b * 3) * h * h;
    for (int idx = t; idx < 17 * W; idx += 1024) {
        int yy = idx / W, xx = idx - yy * W;
        int gx = min(xx, h - 1), gy = min(y0 + yy, h - 1);
        const float* p = db + gy * h + gx;
        sv[yy * S + xx] = scs[0] * p[0] + scs[1] * p[h * h] + scs[2] * p[2 * h * h];
    }
    __syncthreads();
    for (int idx = t; idx < (h << 4); idx += 1024) {
        int oy = idx >> lg, ox = idx & (h - 1);
        float4 q = make_float4(sv[oy * S + ox], sv[oy * S + ox + 1],
                               sv[(oy + 1) * S + ox], sv[(oy + 1) * S + ox + 1]);
        g_q[co2[i] + b * h * h + (y0 + oy) * h + ox] = q;
    }
}

// ---- final gather item (2 rows), 1024 threads ---------------------------------
__device__ __forceinline__ void final_item(int t, int valid, int item,
                                           float* __restrict__ out,
                                           int (*sr0)[7], float (*swy)[7],
                                           float* sob) {
    __syncthreads();   // protect previous item's smem reads
    const int b = item >> 8, yp = item & 255;
    if (valid) {
        if (t < 32) {
            float v = 0.f;
            if (t < 21) {
                int c = t / 7, ii = t - c * 7;
                float mn;
                float sc = calc_scale((b * 3 + c) * 7 + ii, ii, &mn);
                v = -mn * sc;
            }
            for (int o = 16; o; o >>= 1) v += __shfl_xor_sync(~0u, v, o);
            if (t == 0) sob[0] = v;
        }
        if (t >= 64 && t < 78) {
            int k = t - 64;
            int r = k / 7, ii = k - r * 7;
            int hh = 256 >> ii;
            int yy = 2 * yp + r;
            float fy = fminf(fmaxf((yy + 0.5f) * (float)hh * (1.f / 512.f) - 0.5f, 0.f),
                             (float)(hh - 1));
            int y0 = (int)fy;
            swy[r][ii] = fy - (float)y0;
            sr0[r][ii] = y0 * hh;
        }
    }
    __syncthreads();
    if (valid) {
        const int r = t >> 9;
        const int x = t & 511;
        const int y = 2 * yp + r;
        float acc = 0.f;
#pragma unroll
        for (int i = 0; i < 7; i++) {
            const int hh = 256 >> i;
            float fx = fminf(fmaxf((x + 0.5f) * (float)hh * (1.f / 512.f) - 0.5f, 0.f),
                             (float)(hh - 1));
            int x0 = (int)fx;
            float wx = fx - (float)x0;
            float4 p = g_q[co2[i] + (size_t)b * hh * hh + sr0[r][i] + x0];
            float v0 = fmaf(wx, p.y - p.x, p.x);
            float v1 = fmaf(wx, p.w - p.z, p.z);
            acc += fmaf(swy[r][i], v1 - v0, v0);
        }
        out[((size_t)b << 18) + y * 512 + x] = acc + sob[0];
    }
}

// ---- the persistent kernel -----------------------------------------------------
__global__ void __launch_bounds__(1024, 1) k_all(const float* __restrict__ x,
                                                 float* __restrict__ out) {
    extern __shared__ float sm[];
    __shared__ unsigned s_sense;
    __shared__ unsigned t_mn[3], t_mx[3], t_tile[48];
    __shared__ float t_s[3], scs[3];
    __shared__ int sr0[2][7];
    __shared__ float swy[2][7], sob[1];
    const int t = threadIdx.x;
    const int B = blockIdx.x;
    if (t == 0) s_sense = 0u;
    if (B == 0 && t < 168) { g_dmn[t] = 0xFFFFFFFFu; g_dmx[t] = 0u; g_tsum[t] = 0.f; }

#define GBAR() do {                                                        \
        __syncthreads();                                                   \
        if (t == 0) {                                                      \
            unsigned ns = s_sense ^ 1u;                                    \
            __threadfence();                                               \
            if (atomicAdd(&g_cnt, 1u) == NBLK - 1u) {                      \
                atomicExch(&g_cnt, 0u);                                    \
                __threadfence();                                           \
                g_sense = ns;                                              \
            } else {                                                       \
                while (g_sense != ns) __nanosleep(64);                     \
            }                                                              \
            s_sense = ns;                                                  \
        }                                                                  \
        __syncthreads();                                                   \
    } while (0)

    const int tl = t & 511, half = t >> 9;
    float* s_in  = sm + half * 4128;
    float* s_h   = s_in + 2448;
    float* south = s_h + 1152;                    // 512 floats
    unsigned* stat = (unsigned*)(south + 512);    // 10 words

    // ---- P1: x -> L1 (3072 tiles) ----
    for (int it = 0; it < 11; it++) {
        int item = it * (NBLK * 2) + B * 2 + half;
        int valid = item < 3072;
        int ci = min(item, 3071);
        int tx = ci & 7, ty = (ci >> 3) & 15, bc = ci >> 7;
        pyr_tile(tl, valid, 512, x + (size_t)bc * 262144,
                 g_pyr + (size_t)bc * 65536, tx * 32, ty * 16, s_in, s_h, 0);
    }
    GBAR();
    // ---- P2: L1 -> L2 + diff0 (768 tiles) ----
    for (int it = 0; it < 3; it++) {
        int item = it * (NBLK * 2) + B * 2 + half;
        int valid = item < 768;
        int ci = min(item, 767);
        int tx = ci & 3, ty = (ci >> 2) & 7, bc = ci >> 5;
        pd_tile(tl, valid, 0, bc, tx, ty, s_in, s_h, south, stat);
    }
    GBAR();
    // ---- P3: L2 -> L3 + diff1 (192 tiles) ----
    {
        int item = B * 2 + half;
        int valid = item < 192;
        int ci = min(item, 191);
        int tx = ci & 1, ty = (ci >> 1) & 3, bc = ci >> 3;
        pd_tile(tl, valid, 1, bc, tx, ty, s_in, s_h, south, stat);
    }
    GBAR();
    // ---- P4: tail (blocks 0..7) + comb strips (blocks 8..147) ----
    if (B < 8) {
        float* F0 = sm;            // 3 * 4096
        float* F1 = sm + 12288;    // 3 * 1024
        float* H  = sm + 15360;    // 3 * 2048
        if (t < 3) { t_mn[t] = 0xFFFFFFFFu; t_mx[t] = 0u; }
        if (t < 48) t_tile[t] = 0u;
        const float4* src = (const float4*)(g_pyr + c_off[2] + (size_t)(B * 3) * 4096);
        float4* F4 = (float4*)F0;
        for (int idx = t; idx < 3072; idx += 1024) F4[idx] = src[idx];
        __syncthreads();
        tail_stage<6>(t, B, F0, 4096, F1, 1024, H, t_mn, t_mx, t_tile, t_s);
        tail_stage<5>(t, B, F1, 1024, F0, 4096, H, t_mn, t_mx, t_tile, t_s);
        tail_stage<4>(t, B, F0, 4096, F1, 1024, H, t_mn, t_mx, t_tile, t_s);
        tail_stage<3>(t, B, F1, 1024, F0, 4096, H, t_mn, t_mx, t_tile, t_s);
        tail_stage<2>(t, B, F0, 4096, F1, 1024, H, t_mn, t_mx, t_tile, t_s);
    } else {
        for (int k = B - 8; k < 192; k += 140) comb_strip(t, k, sm, scs);
    }
    GBAR();
    // ---- P5: final gather (2048 row-pair items) ----
    for (int it = 0; it < 14; it++) {
        int item = it * NBLK + B;
        final_item(t, item < 2048, min(item, 2047), out, sr0, swy, sob);
    }
#undef GBAR
}

extern "C" void kernel_launch(void* const* d_in, const int* in_sizes, int n_in,
                              void* d_out, int out_size) {
    const float* x = (const float*)d_in[0];
    float* out = (float*)d_out;
    static int configured = 0;
    if (!configured) {
        cudaFuncSetAttribute(k_all, cudaFuncAttributeMaxDynamicSharedMemorySize, 122880);
        configured = 1;
    }
    // 122880B dyn smem (>228KB/2) + __launch_bounds__(1024,1) => 1 block/SM,
    // grid=148 <= SM count => all blocks resident => global barrier is safe.
    k_all<<<NBLK, 1024, 122880>>>(x, out);
}

// round 10
// speedup vs baseline: 1.0666x; 1.0666x over previous
#include <cuda_runtime.h>
#include <math_constants.h>

// ---------------------------------------------------------------------------
// IttiKochSaliency, x[8,3,512,512] -> out[8,512,512]  —  persistent kernel v2
//
// 296 blocks x 512 threads, >=2 blocks/SM resident (28KB smem, lb(512,2)),
// sense-reversing global barrier between phases. Each block owns its tiles
// with its OWN __syncthreads (no cross-tile coupling, 2+ tiles overlap/SM).
//   P1: x -> L1 (3072 tiles)                P4: tail per-(b,c) (24 blocks) +
//   P2: L1 -> L2 + diff0 + stats (768)          comb strips i=0,1 (192 blocks)
//   P3: L2 -> L3 + diff1 + stats (192)      P5: comb i=2..6 (40 blocks)
//                                           P6: final gather (4096 rows)
// ---------------------------------------------------------------------------

__device__ float    g_pyr[2064384];   // L1,L2,L3 per bc
__device__ float    g_d[1966080];     // diff maps i=0,1
__device__ float    g_d2[130944];     // diff maps i=2..6 per bc (5456 each)
__device__ float4   g_q[699008];      // quad-dup combined maps per (b,i)
__device__ unsigned g_dmn[168], g_dmx[168];
__device__ float    g_tsum[168];
__device__ unsigned g_cnt = 0u;
__device__ volatile unsigned g_sense = 0u;

__constant__ int c_off[3] = {0, 1572864, 1966080};
__constant__ int co2[7]   = {0, 524288, 655360, 688128, 696320, 698368, 698880};
__constant__ int d2off[5] = {0, 4096, 5120, 5376, 5440};

#define NBLK 296

__device__ __forceinline__ int refl(int t, int n) {
    return t < 0 ? -t : (t >= n ? 2 * n - 2 - t : t);
}
__device__ __forceinline__ float calc_scale(int sidx, int i, float* mn_out) {
    float mn = __uint_as_float(g_dmn[sidx]);
    float mx = __uint_as_float(g_dmx[sidx]);
    float inv = 1.f / (mx - mn);
    int n = (16 >> i) - 1;
    float lm = (n > 0) ? (g_tsum[sidx] / (float)(n * n) - mn) * inv : 0.f;
    float om = 1.f - lm;
    *mn_out = mn;
    return om * om * inv * (1.f / 3.f);
}

#define W0 0.03125f
#define W1 0.15625f
#define W2 0.3125f

// ---- separable pyrdown tile (32x16 out), 512 threads -------------------------
__device__ __forceinline__ void pyr_tile(int t, int valid, int HI,
                                         const float* __restrict__ in,
                                         float* __restrict__ outp,
                                         int ox0, int oy0,
                                         float* s_in, float* s_h, float* sout) {
    const int HO = HI >> 1;
    const int iy0 = 2 * oy0 - 2, ix0 = 2 * ox0 - 2;
    if (valid) {
        for (int idx = t; idx < 36 * 34; idx += 512) {
            int r = idx / 34, c2 = idx - r * 34;
            int gy = refl(iy0 + r, HI);
            int ix = ix0 + 2 * c2;
            float v0, v1;
            if (ix >= 0 && ix + 2 <= HI) {
                float2 p = *(const float2*)(in + gy * HI + ix);
                v0 = p.x; v1 = p.y;
            } else {
                v0 = in[gy * HI + refl(ix, HI)];
                v1 = in[gy * HI + refl(ix + 1, HI)];
            }
            s_in[r * 68 + 2 * c2] = v0;
            s_in[r * 68 + 2 * c2 + 1] = v1;
        }
    }
    __syncthreads();
    if (valid) {
        for (int idx = t; idx < 36 * 32; idx += 512) {
            int r = idx >> 5, c = idx & 31;
            const float* p = s_in + r * 68 + 2 * c;
            s_h[idx] = W0 * (p[0] + p[5]) + W1 * (p[1] + p[4]) + W2 * (p[2] + p[3]);
        }
    }
    __syncthreads();
    if (valid) {
        const int tx = t & 31, ty = t >> 5;
        const float* q = s_h + 2 * ty * 32 + tx;
        float acc = W0 * (q[0] + q[160]) + W1 * (q[32] + q[128]) + W2 * (q[64] + q[96]);
        outp[(oy0 + ty) * HO + ox0 + tx] = acc;
        if (sout) sout[ty * 32 + tx] = acc;
    }
    __syncthreads();
}

// ---- pyrdown + fused diff (I = 0 or 1), 512 threads ---------------------------
__device__ __forceinline__ void pd_tile(int t, int valid, int I, int bc,
                                        int tilex, int tiley,
                                        float* s_in, float* s_h, float* sout,
                                        unsigned* stat) {
    const int HI = 256 >> I;
    const int ox0 = tilex * 32, oy0 = tiley * 16;
    if (valid) {
        if (t == 0) { stat[0] = 0xFFFFFFFFu; stat[1] = 0u; }
        if (t < 8) stat[2 + t] = 0u;
    }
    const float* in = g_pyr + c_off[I] + (size_t)bc * HI * HI;
    float* outp = g_pyr + c_off[I + 1] + (size_t)bc * (HI >> 1) * (HI >> 1);
    pyr_tile(t, valid, HI, in, outp, ox0, oy0, s_in, s_h, sout);
    if (valid) {
        const int p4 = t * 4;
        const int ly = p4 >> 6, lx = p4 & 63;
        const float* fr = s_in + (ly + 2) * 68 + lx + 2;
        const float c0 = sout[(ly >> 1) * 32 + (lx >> 1)];
        const float c1 = sout[(ly >> 1) * 32 + (lx >> 1) + 1];
        float d0 = fabsf(fr[0] - c0), d1 = fabsf(fr[1] - c0);
        float d2 = fabsf(fr[2] - c1), d3 = fabsf(fr[3] - c1);
        float* gd = g_d + (I ? 1572864 : 0) + (size_t)bc * HI * HI;
        *(float4*)(gd + (2 * oy0 + ly) * HI + 2 * ox0 + lx) = make_float4(d0, d1, d2, d3);
        float mx4 = fmaxf(fmaxf(d0, d1), fmaxf(d2, d3));
        float mn4 = fminf(fminf(d0, d1), fminf(d2, d3));
        float tm = mx4;
        tm = fmaxf(tm, __shfl_xor_sync(~0u, tm, 1, 4));
        tm = fmaxf(tm, __shfl_xor_sync(~0u, tm, 2, 4));
        if ((t & 3) == 0)
            atomicMax(&stat[2 + (ly >> 4) * 4 + (lx >> 4)], __float_as_uint(tm));
        for (int o = 16; o; o >>= 1) {
            mx4 = fmaxf(mx4, __shfl_xor_sync(~0u, mx4, o));
            mn4 = fminf(mn4, __shfl_xor_sync(~0u, mn4, o));
        }
        if ((t & 31) == 0) {
            atomicMax(&stat[1], __float_as_uint(mx4));
            atomicMin(&stat[0], __float_as_uint(mn4));
        }
    }
    __syncthreads();
    if (valid) {
        const int sidx = bc * 7 + I;
        if (t == 0) { atomicMin(&g_dmn[sidx], stat[0]); atomicMax(&g_dmx[sidx], stat[1]); }
        if (t < 8) {
            const int NT = (16 >> I) - 1;
            int gtc = 4 * tilex + (t & 3);
            int gtr = 2 * tiley + (t >> 2);
            if (gtc < NT && gtr < NT)
                atomicAdd(&g_tsum[sidx], __uint_as_float(stat[2 + t]));
        }
    }
    __syncthreads();
}

// ---- one per-channel tail stage, 512 threads, per-stage stat slots ------------
template <int LGF>
__device__ __forceinline__ void tail_stage2(int t, int bc, float* F, float* C,
                                            float* H, unsigned* t_mn,
                                            unsigned* t_mx, unsigned* t_tile) {
    constexpr int HF = 1 << LGF, HC = HF >> 1;
    constexpr int S = 6 - LGF;   // stage index 0..4
    constexpr int OFF = (LGF == 6) ? 0 : (LGF == 5) ? 4096 :
                        (LGF == 4) ? 5120 : (LGF == 3) ? 5376 : 5440;
    for (int idx = t; idx < HF * HC; idx += 512) {
        int r = idx >> (LGF - 1);
        const float* row = F + (r << LGF);
        int c0 = 2 * (idx & (HC - 1));
        H[idx] = W0 * (row[refl(c0 - 2, HF)] + row[refl(c0 + 3, HF)])
               + W1 * (row[refl(c0 - 1, HF)] + row[refl(c0 + 2, HF)])
               + W2 * (row[c0] + row[c0 + 1]);
    }
    __syncthreads();
    float* gd2 = g_d2 + bc * 5456 + OFF;
    for (int idx = t; idx < HC * HC; idx += 512) {
        int oy = idx >> (LGF - 1), ox = idx & (HC - 1);
        int r0 = 2 * oy;
        float cv = W0 * (H[(refl(r0 - 2, HF) << (LGF - 1)) + ox] +
                         H[(refl(r0 + 3, HF) << (LGF - 1)) + ox])
                 + W1 * (H[(refl(r0 - 1, HF) << (LGF - 1)) + ox] +
                         H[(refl(r0 + 2, HF) << (LGF - 1)) + ox])
                 + W2 * (H[(r0 << (LGF - 1)) + ox] + H[((r0 + 1) << (LGF - 1)) + ox]);
        C[idx] = cv;
        int f0 = (oy << (LGF + 1)) + 2 * ox;
        float d00 = fabsf(F[f0] - cv),      d01 = fabsf(F[f0 + 1] - cv);
        float d10 = fabsf(F[f0 + HF] - cv), d11 = fabsf(F[f0 + HF + 1] - cv);
        F[f0] = d00; F[f0 + 1] = d01; F[f0 + HF] = d10; F[f0 + HF + 1] = d11;
        *(float2*)(gd2 + f0) = make_float2(d00, d01);
        *(float2*)(gd2 + f0 + HF) = make_float2(d10, d11);
        float mx4 = fmaxf(fmaxf(d00, d01), fmaxf(d10, d11));
        float mn4 = fminf(fminf(d00, d01), fminf(d10, d11));
        if (LGF >= 4) {   // item counts are multiples of 32 -> full warps
            float a = mx4, n2 = mn4;
            for (int o = 16; o; o >>= 1) {
                a = fmaxf(a, __shfl_xor_sync(~0u, a, o));
                n2 = fminf(n2, __shfl_xor_sync(~0u, n2, o));
            }
            if ((t & 31) == 0) {
                atomicMax(&t_mx[S], __float_as_uint(a));
                atomicMin(&t_mn[S], __float_as_uint(n2));
            }
        } else {
            atomicMax(&t_mx[S], __float_as_uint(mx4));
            atomicMin(&t_mn[S], __float_as_uint(mn4));
        }
        if (LGF == 6)
            atomicMax(&t_tile[(oy >> 3) * 4 + (ox >> 3)], __float_as_uint(mx4));
        else if (LGF == 5) {
            if (oy < 8 && ox < 8) atomicMax(&t_tile[16], __float_as_uint(mx4));
        }
    }
    __syncthreads();
}

// ---- comb strip for i=0,1 (full-width 16-row strip), 512 threads ---------------
__device__ __forceinline__ void comb_strip(int t, int k, float* sm, float* scs) {
    int i, b, y0, lg;
    if (k < 128) { i = 0; b = k >> 4; y0 = (k & 15) * 16; lg = 8; }
    else { int r = k - 128; i = 1; b = r >> 3; y0 = (r & 7) * 16; lg = 7; }
    const int h = 1 << lg, S = h + 2, W = h + 1;
    float* sv = sm;
    if (t < 3) { float mn; scs[t] = calc_scale((b * 3 + t) * 7 + i, i, &mn); }
    __syncthreads();
    const float* db = g_d + (i ? 1572864 : 0) + (size_t)(b * 3) * h * h;
    for (int idx = t; idx < 17 * W; idx += 512) {
        int yy = idx / W, xx = idx - yy * W;
        int gx = min(xx, h - 1), gy = min(y0 + yy, h - 1);
        const float* p = db + gy * h + gx;
        sv[yy * S + xx] = scs[0] * p[0] + scs[1] * p[h * h] + scs[2] * p[2 * h * h];
    }
    __syncthreads();
    for (int idx = t; idx < (h << 4); idx += 512) {
        int oy = idx >> lg, ox = idx & (h - 1);
        float4 q = make_float4(sv[oy * S + ox], sv[oy * S + ox + 1],
                               sv[(oy + 1) * S + ox], sv[(oy + 1) * S + ox + 1]);
        g_q[co2[i] + b * h * h + (y0 + oy) * h + ox] = q;
    }
}

// ---- comb for one (b, i>=2) level, 512 threads ---------------------------------
__device__ __forceinline__ void comb_small(int t, int k, float* sm, float* scs) {
    const int b = k / 5, i2 = k - b * 5, i = 2 + i2;
    const int h = 64 >> i2, hp = h + 1, S = h + 2;
    float* sv = sm;
    if (t < 3) { float mn; scs[t] = calc_scale((b * 3 + t) * 7 + i, i, &mn); }
    __syncthreads();
    const float* db = g_d2 + d2off[i2];
    for (int idx = t; idx < hp * hp; idx += 512) {
        int yy = idx / hp, xx = idx - yy * hp;
        int gx = min(xx, h - 1), gy = min(yy, h - 1);
        int p = gy * h + gx;
        sv[yy * S + xx] = scs[0] * db[(b * 3) * 5456 + p]
                        + scs[1] * db[(b * 3 + 1) * 5456 + p]
                        + scs[2] * db[(b * 3 + 2) * 5456 + p];
    }
    __syncthreads();
    for (int idx = t; idx < h * h; idx += 512) {
        int oy = idx / h, ox = idx - oy * h;
        float4 q = make_float4(sv[oy * S + ox], sv[oy * S + ox + 1],
                               sv[(oy + 1) * S + ox], sv[(oy + 1) * S + ox + 1]);
        g_q[co2[i] + b * h * h + idx] = q;
    }
}

// ---- final gather: one row (512 px), 512 threads --------------------------------
__device__ __forceinline__ void final_row(int t, int valid, int item,
                                          float* __restrict__ out,
                                          int* sr0, float* swy, float* sob) {
    __syncthreads();
    const int b = item >> 9, y = item & 511;
    if (valid) {
        if (t < 32) {
            float v = 0.f;
            if (t < 21) {
                int c = t / 7, ii = t - c * 7;
                float mn;
                float sc = calc_scale((b * 3 + c) * 7 + ii, ii, &mn);
                v = -mn * sc;
            }
            for (int o = 16; o; o >>= 1) v += __shfl_xor_sync(~0u, v, o);
            if (t == 0) sob[0] = v;
        }
        if (t >= 32 && t < 39) {
            int ii = t - 32;
            int hh = 256 >> ii;
            float fy = fminf(fmaxf((y + 0.5f) * (float)hh * (1.f / 512.f) - 0.5f, 0.f),
                             (float)(hh - 1));
            int y0 = (int)fy;
            swy[ii] = fy - (float)y0;
            sr0[ii] = y0 * hh;
        }
    }
    __syncthreads();
    if (valid) {
        const int x = t;
        float acc = 0.f;
#pragma unroll
        for (int i = 0; i < 7; i++) {
            const int hh = 256 >> i;
            float fx = fminf(fmaxf((x + 0.5f) * (float)hh * (1.f / 512.f) - 0.5f, 0.f),
                             (float)(hh - 1));
            int x0 = (int)fx;
            float wx = fx - (float)x0;
            float4 p = g_q[co2[i] + (size_t)b * hh * hh + sr0[i] + x0];
            float v0 = fmaf(wx, p.y - p.x, p.x);
            float v1 = fmaf(wx, p.w - p.z, p.z);
            acc += fmaf(swy[i], v1 - v0, v0);
        }
        out[((size_t)b << 18) + y * 512 + x] = acc + sob[0];
    }
}

// ---- the persistent kernel -------------------------------------------------------
__global__ void __launch_bounds__(512, 2) k_all(const float* __restrict__ x,
                                                float* __restrict__ out) {
    extern __shared__ float sm[];
    __shared__ unsigned s_sense;
    __shared__ unsigned pstat[10];
    __shared__ unsigned t_mn[5], t_mx[5], t_tile[17];
    __shared__ float scs[3];
    __shared__ int sr0[7];
    __shared__ float swy[7], sob[1];
    const int t = threadIdx.x;
    const int B = blockIdx.x;
    if (t == 0) s_sense = g_sense;
    if (B == 0 && t < 168) { g_dmn[t] = 0xFFFFFFFFu; g_dmx[t] = 0u; g_tsum[t] = 0.f; }

#define GBAR() do {                                                        \
        __syncthreads();                                                   \
        if (t == 0) {                                                      \
            unsigned ns = s_sense ^ 1u;                                    \
            __threadfence();                                               \
            if (atomicAdd(&g_cnt, 1u) == NBLK - 1u) {                      \
                atomicExch(&g_cnt, 0u);                                    \
                __threadfence();                                           \
                g_sense = ns;                                              \
            } else {                                                       \
                while (g_sense != ns) __nanosleep(64);                     \
            }                                                              \
            s_sense = ns;                                                  \
        }                                                                  \
        __syncthreads();                                                   \
    } while (0)

    float* s_in = sm;                 // 2448
    float* s_h  = sm + 2448;          // 1152
    float* sout = sm + 3600;          // 512

    // ---- P1: x -> L1 (3072 tiles) ----
    for (int it = 0; it < 11; it++) {
        int item = it * NBLK + B;
        int valid = item < 3072;
        int ci = valid ? item : 0;
        int tx = ci & 7, ty = (ci >> 3) & 15, bc = ci >> 7;
        pyr_tile(t, valid, 512, x + (size_t)bc * 262144,
                 g_pyr + (size_t)bc * 65536, tx * 32, ty * 16, s_in, s_h, 0);
    }
    GBAR();
    // ---- P2: L1 -> L2 + diff0 (768 tiles) ----
    for (int it = 0; it < 3; it++) {
        int item = it * NBLK + B;
        int valid = item < 768;
        int ci = valid ? item : 0;
        int tx = ci & 3, ty = (ci >> 2) & 7, bc = ci >> 5;
        pd_tile(t, valid, 0, bc, tx, ty, s_in, s_h, sout, pstat);
    }
    GBAR();
    // ---- P3: L2 -> L3 + diff1 (192 tiles) ----
    {
        int valid = B < 192;
        int ci = valid ? B : 0;
        int tx = ci & 1, ty = (ci >> 1) & 3, bc = ci >> 3;
        pd_tile(t, valid, 1, bc, tx, ty, s_in, s_h, sout, pstat);
    }
    GBAR();
    // ---- P4: per-channel tail (blocks 0..23) + comb strips i=0,1 (24..215) ----
    if (B < 24) {
        float* F0 = sm;          // 4096
        float* F1 = sm + 4096;   // 1024
        float* H  = sm + 5120;   // 2048
        if (t < 5) { t_mn[t] = 0xFFFFFFFFu; t_mx[t] = 0u; }
        if (t < 17) t_tile[t] = 0u;
        const float4* src = (const float4*)(g_pyr + c_off[2] + (size_t)B * 4096);
        float4* F4 = (float4*)F0;
        for (int idx = t; idx < 1024; idx += 512) F4[idx] = src[idx];
        __syncthreads();
        tail_stage2<6>(t, B, F0, F1, H, t_mn, t_mx, t_tile);
        tail_stage2<5>(t, B, F1, F0, H, t_mn, t_mx, t_tile);
        tail_stage2<4>(t, B, F0, F1, H, t_mn, t_mx, t_tile);
        tail_stage2<3>(t, B, F1, F0, H, t_mn, t_mx, t_tile);
        tail_stage2<2>(t, B, F0, F1, H, t_mn, t_mx, t_tile);
        if (t < 5) {
            const int s = t, I = s + 2, sidx = B * 7 + I;
            float ts = 0.f;
            if (s == 0) {
                for (int k = 0; k < 3; k++)
                    for (int j = 0; j < 3; j++) ts += __uint_as_float(t_tile[k * 4 + j]);
            } else if (s == 1) ts = __uint_as_float(t_tile[16]);
            g_dmn[sidx] = t_mn[s];
            g_dmx[sidx] = t_mx[s];
            g_tsum[sidx] = ts;
        }
    } else if (B < 216) {
        comb_strip(t, B - 24, sm, scs);
    }
    GBAR();
    // ---- P5: comb i=2..6 (40 blocks) ----
    if (B < 40) comb_small(t, B, sm, scs);
    GBAR();
    // ---- P6: final gather (4096 rows) ----
    for (int it = 0; it < 14; it++) {
        int item = it * NBLK + B;
        int valid = item < 4096;
        final_row(t, valid, valid ? item : 0, out, sr0, swy, sob);
    }
#undef GBAR
}

extern "C" void kernel_launch(void* const* d_in, const int* in_sizes, int n_in,
                              void* d_out, int out_size) {
    const float* x = (const float*)d_in[0];
    float* out = (float*)d_out;
    // 28672B dyn smem + __launch_bounds__(512,2) => >=2 blocks/SM resident,
    // grid 296 <= 2*148 => all blocks resident => global barrier is safe.
    k_all<<<NBLK, 512, 28672>>>(x, out);
}

// round 11
// speedup vs baseline: 1.1333x; 1.0625x over previous
#include <cuda_runtime.h>
#include <math_constants.h>

// ---------------------------------------------------------------------------
// IttiKochSaliency, x[8,3,512,512] -> out[8,512,512]
//
// 5 launches (R8 champion structure, rebalanced):
//  k_pyr0 : x -> L1 (256^2), separable 6-tap stride-2 reflect (+ stat init)
//  k_pd<1>: L1 -> L2 + diff0 + stats (768 tiles)
//  k_tail : blocks 0..23  -> per-(b,c): load L2 (smem), compute L3 in smem,
//           diff1 + direct stats, then stage chain i=2..6 (diffs -> g_d2,
//           direct stats);  blocks 24..151 -> comb strips i=0 (overlap)
//  k_comb : strips i=1 (64 blocks) + comb_small i=2..6 (40 blocks)
//  k_final: 7-level bilinear gather, 1 LDG.128 per level per pixel
// ---------------------------------------------------------------------------

__device__ float    g_pyr[1966080];   // L1 (256^2/bc @0), L2 (128^2/bc @1572864)
__device__ float    g_d[1966080];     // diff0 @0 (256^2/bc), diff1 @1572864 (128^2/bc)
__device__ float    g_d2[130944];     // diffs i=2..6 per bc (5456 each)
__device__ float4   g_q[699008];      // quad-dup combined maps per (b,i)
__device__ unsigned g_dmn[168], g_dmx[168];
__device__ float    g_tsum[168];

__constant__ int co2[7]   = {0, 524288, 655360, 688128, 696320, 698368, 698880};
__constant__ int d2off[5] = {0, 4096, 5120, 5376, 5440};

__device__ __forceinline__ int refl(int t, int n) {
    return t < 0 ? -t : (t >= n ? 2 * n - 2 - t : t);
}
__device__ __forceinline__ float calc_scale(int sidx, int i, float* mn_out) {
    float mn = __uint_as_float(g_dmn[sidx]);
    float mx = __uint_as_float(g_dmx[sidx]);
    float inv = 1.f / (mx - mn);
    int n = (16 >> i) - 1;
    float lm = (n > 0) ? (g_tsum[sidx] / (float)(n * n) - mn) * inv : 0.f;
    float om = 1.f - lm;
    *mn_out = mn;
    return om * om * inv * (1.f / 3.f);
}

#define W0 0.03125f
#define W1 0.15625f
#define W2 0.3125f

// ---------------- level 0 pyrdown: 512 -> 256 (unchanged, proven) ------------
__global__ void __launch_bounds__(512) k_pyr0(const float* __restrict__ x) {
    constexpr int HI = 512, HO = 256;
    __shared__ float s_in[36 * 68];
    __shared__ float s_h[36 * 32];
    const int t = threadIdx.x;
    if (blockIdx.x == 0 && blockIdx.y == 0 && blockIdx.z == 0 && t < 168) {
        g_dmn[t] = 0xFFFFFFFFu; g_dmx[t] = 0u; g_tsum[t] = 0.f;
    }
    const int bc = blockIdx.z;
    const int ox0 = blockIdx.x * 32, oy0 = blockIdx.y * 16;
    const float* in = x + (size_t)bc * HI * HI;
    float* out = g_pyr + (size_t)bc * HO * HO;
    const int iy0 = 2 * oy0 - 2, ix0 = 2 * ox0 - 2;
    for (int idx = t; idx < 36 * 34; idx += 512) {
        int r = idx / 34, c2 = idx - r * 34;
        int gy = refl(iy0 + r, HI);
        int ix = ix0 + 2 * c2;
        float v0, v1;
        if (ix >= 0 && ix + 2 <= HI) {
            float2 p = *(const float2*)(in + gy * HI + ix);
            v0 = p.x; v1 = p.y;
        } else {
            v0 = in[gy * HI + refl(ix, HI)];
            v1 = in[gy * HI + refl(ix + 1, HI)];
        }
        s_in[r * 68 + 2 * c2] = v0;
        s_in[r * 68 + 2 * c2 + 1] = v1;
    }
    __syncthreads();
    for (int idx = t; idx < 36 * 32; idx += 512) {
        int r = idx >> 5, c = idx & 31;
        const float* p = s_in + r * 68 + 2 * c;
        s_h[idx] = W0 * (p[0] + p[5]) + W1 * (p[1] + p[4]) + W2 * (p[2] + p[3]);
    }
    __syncthreads();
    const int tx = t & 31, ty = t >> 5;
    const float* q = s_h + 2 * ty * 32 + tx;
    float acc = W0 * (q[0] + q[160]) + W1 * (q[32] + q[128]) + W2 * (q[64] + q[96]);
    out[(oy0 + ty) * HO + ox0 + tx] = acc;
}

// ---------------- pyrdown + fused diff0 (unchanged, proven) -------------------
__global__ void __launch_bounds__(512) k_pd1() {
    constexpr int HI = 256;
    constexpr int NT = 15;
    __shared__ float s_in[36 * 68];
    __shared__ float s_h[36 * 32];
    __shared__ float sout[16 * 32];
    __shared__ unsigned s_mn, s_mx, stile[8];
    const int t = threadIdx.x;
    if (t == 0) { s_mn = 0xFFFFFFFFu; s_mx = 0u; }
    if (t < 8) stile[t] = 0u;
    const int bc = blockIdx.z;
    const int ox0 = blockIdx.x * 32, oy0 = blockIdx.y * 16;
    const float* in = g_pyr + (size_t)bc * HI * HI;
    float* outp = g_pyr + 1572864 + (size_t)bc * 16384;
    const int iy0 = 2 * oy0 - 2, ix0 = 2 * ox0 - 2;
    for (int idx = t; idx < 36 * 34; idx += 512) {
        int r = idx / 34, c2 = idx - r * 34;
        int gy = refl(iy0 + r, HI);
        int ix = ix0 + 2 * c2;
        float v0, v1;
        if (ix >= 0 && ix + 2 <= HI) {
            float2 p = *(const float2*)(in + gy * HI + ix);
            v0 = p.x; v1 = p.y;
        } else {
            v0 = in[gy * HI + refl(ix, HI)];
            v1 = in[gy * HI + refl(ix + 1, HI)];
        }
        s_in[r * 68 + 2 * c2] = v0;
        s_in[r * 68 + 2 * c2 + 1] = v1;
    }
    __syncthreads();
    for (int idx = t; idx < 36 * 32; idx += 512) {
        int r = idx >> 5, c = idx & 31;
        const float* p = s_in + r * 68 + 2 * c;
        s_h[idx] = W0 * (p[0] + p[5]) + W1 * (p[1] + p[4]) + W2 * (p[2] + p[3]);
    }
    __syncthreads();
    {
        const int tx = t & 31, ty = t >> 5;
        const float* q = s_h + 2 * ty * 32 + tx;
        float acc = W0 * (q[0] + q[160]) + W1 * (q[32] + q[128]) + W2 * (q[64] + q[96]);
        outp[(oy0 + ty) * 128 + ox0 + tx] = acc;
        sout[ty * 32 + tx] = acc;
    }
    __syncthreads();
    {
        const int p = t * 4;
        const int ly = p >> 6, lx = p & 63;
        const float* fr = s_in + (ly + 2) * 68 + lx + 2;
        const float c0 = sout[(ly >> 1) * 32 + (lx >> 1)];
        const float c1 = sout[(ly >> 1) * 32 + (lx >> 1) + 1];
        float d0 = fabsf(fr[0] - c0), d1 = fabsf(fr[1] - c0);
        float d2 = fabsf(fr[2] - c1), d3 = fabsf(fr[3] - c1);
        float* gd = g_d + (size_t)bc * 65536;
        *(float4*)(gd + (2 * oy0 + ly) * 256 + 2 * ox0 + lx) = make_float4(d0, d1, d2, d3);
        float mx4 = fmaxf(fmaxf(d0, d1), fmaxf(d2, d3));
        float mn4 = fminf(fminf(d0, d1), fminf(d2, d3));
        float tm = mx4;
        tm = fmaxf(tm, __shfl_xor_sync(~0u, tm, 1, 4));
        tm = fmaxf(tm, __shfl_xor_sync(~0u, tm, 2, 4));
        if ((t & 3) == 0)
            atomicMax(&stile[(ly >> 4) * 4 + (lx >> 4)], __float_as_uint(tm));
        for (int o = 16; o; o >>= 1) {
            mx4 = fmaxf(mx4, __shfl_xor_sync(~0u, mx4, o));
            mn4 = fminf(mn4, __shfl_xor_sync(~0u, mn4, o));
        }
        if ((t & 31) == 0) {
            atomicMax(&s_mx, __float_as_uint(mx4));
            atomicMin(&s_mn, __float_as_uint(mn4));
        }
    }
    __syncthreads();
    const int sidx = bc * 7;
    if (t == 0) { atomicMin(&g_dmn[sidx], s_mn); atomicMax(&g_dmx[sidx], s_mx); }
    if (t < 8) {
        int gtc = 4 * blockIdx.x + (t & 3);
        int gtr = 2 * blockIdx.y + (t >> 2);
        if (gtc < NT && gtr < NT)
            atomicAdd(&g_tsum[sidx], __uint_as_float(stile[t]));
    }
}

// ---- per-channel tail stage (R10-proven, 1024-thread stride) -----------------
template <int LGF>
__device__ __forceinline__ void tail_stage2(int t, int bc, float* F, float* C,
                                            float* H, unsigned* t_mn,
                                            unsigned* t_mx, unsigned* t_tile) {
    constexpr int HF = 1 << LGF, HC = HF >> 1;
    constexpr int S = 6 - LGF;
    constexpr int OFF = (LGF == 6) ? 0 : (LGF == 5) ? 4096 :
                        (LGF == 4) ? 5120 : (LGF == 3) ? 5376 : 5440;
    for (int idx = t; idx < HF * HC; idx += 1024) {
        int r = idx >> (LGF - 1);
        const float* row = F + (r << LGF);
        int c0 = 2 * (idx & (HC - 1));
        H[idx] = W0 * (row[refl(c0 - 2, HF)] + row[refl(c0 + 3, HF)])
               + W1 * (row[refl(c0 - 1, HF)] + row[refl(c0 + 2, HF)])
               + W2 * (row[c0] + row[c0 + 1]);
    }
    __syncthreads();
    float* gd2 = g_d2 + bc * 5456 + OFF;
    for (int idx = t; idx < HC * HC; idx += 1024) {
        int oy = idx >> (LGF - 1), ox = idx & (HC - 1);
        int r0 = 2 * oy;
        float cv = W0 * (H[(refl(r0 - 2, HF) << (LGF - 1)) + ox] +
                         H[(refl(r0 + 3, HF) << (LGF - 1)) + ox])
                 + W1 * (H[(refl(r0 - 1, HF) << (LGF - 1)) + ox] +
                         H[(refl(r0 + 2, HF) << (LGF - 1)) + ox])
                 + W2 * (H[(r0 << (LGF - 1)) + ox] + H[((r0 + 1) << (LGF - 1)) + ox]);
        C[idx] = cv;
        int f0 = (oy << (LGF + 1)) + 2 * ox;
        float d00 = fabsf(F[f0] - cv),      d01 = fabsf(F[f0 + 1] - cv);
        float d10 = fabsf(F[f0 + HF] - cv), d11 = fabsf(F[f0 + HF + 1] - cv);
        F[f0] = d00; F[f0 + 1] = d01; F[f0 + HF] = d10; F[f0 + HF + 1] = d11;
        *(float2*)(gd2 + f0) = make_float2(d00, d01);
        *(float2*)(gd2 + f0 + HF) = make_float2(d10, d11);
        float mx4 = fmaxf(fmaxf(d00, d01), fmaxf(d10, d11));
        float mn4 = fminf(fminf(d00, d01), fminf(d10, d11));
        if (LGF >= 4) {
            float a = mx4, n2 = mn4;
            for (int o = 16; o; o >>= 1) {
                a = fmaxf(a, __shfl_xor_sync(~0u, a, o));
                n2 = fminf(n2, __shfl_xor_sync(~0u, n2, o));
            }
            if ((t & 31) == 0) {
                atomicMax(&t_mx[S], __float_as_uint(a));
                atomicMin(&t_mn[S], __float_as_uint(n2));
            }
        } else {
            atomicMax(&t_mx[S], __float_as_uint(mx4));
            atomicMin(&t_mn[S], __float_as_uint(mn4));
        }
        if (LGF == 6)
            atomicMax(&t_tile[(oy >> 3) * 4 + (ox >> 3)], __float_as_uint(mx4));
        else if (LGF == 5) {
            if (oy < 8 && ox < 8) atomicMax(&t_tile[16], __float_as_uint(mx4));
        }
    }
    __syncthreads();
}

// ---- comb strip (full-width 16-row strip for i=0,1), stride 1024 -------------
__device__ __forceinline__ void comb_strip(int t, int k, float* sm, float* scs) {
    int i, b, y0, lg;
    if (k < 128) { i = 0; b = k >> 4; y0 = (k & 15) * 16; lg = 8; }
    else { int r = k - 128; i = 1; b = r >> 3; y0 = (r & 7) * 16; lg = 7; }
    const int h = 1 << lg, S = h + 2, W = h + 1;
    float* sv = sm;
    if (t < 3) { float mn; scs[t] = calc_scale((b * 3 + t) * 7 + i, i, &mn); }
    __syncthreads();
    const float* db = g_d + (i ? 1572864 : 0) + (size_t)(b * 3) * h * h;
    for (int idx = t; idx < 17 * W; idx += 1024) {
        int yy = idx / W, xx = idx - yy * W;
        int gx = min(xx, h - 1), gy = min(y0 + yy, h - 1);
        const float* p = db + gy * h + gx;
        sv[yy * S + xx] = scs[0] * p[0] + scs[1] * p[h * h] + scs[2] * p[2 * h * h];
    }
    __syncthreads();
    for (int idx = t; idx < (h << 4); idx += 1024) {
        int oy = idx >> lg, ox = idx & (h - 1);
        float4 q = make_float4(sv[oy * S + ox], sv[oy * S + ox + 1],
                               sv[(oy + 1) * S + ox], sv[(oy + 1) * S + ox + 1]);
        g_q[co2[i] + b * h * h + (y0 + oy) * h + ox] = q;
    }
}

// ---- comb for one (b, i>=2) level, stride 1024 --------------------------------
__device__ __forceinline__ void comb_small(int t, int k, float* sm, float* scs) {
    const int b = k / 5, i2 = k - b * 5, i = 2 + i2;
    const int h = 64 >> i2, hp = h + 1, S = h + 2;
    float* sv = sm;
    if (t < 3) { float mn; scs[t] = calc_scale((b * 3 + t) * 7 + i, i, &mn); }
    __syncthreads();
    const float* db = g_d2 + d2off[i2];
    for (int idx = t; idx < hp * hp; idx += 1024) {
        int yy = idx / hp, xx = idx - yy * hp;
        int gx = min(xx, h - 1), gy = min(yy, h - 1);
        int p = gy * h + gx;
        sv[yy * S + xx] = scs[0] * db[(b * 3) * 5456 + p]
                        + scs[1] * db[(b * 3 + 1) * 5456 + p]
                        + scs[2] * db[(b * 3 + 2) * 5456 + p];
    }
    __syncthreads();
    for (int idx = t; idx < h * h; idx += 1024) {
        int oy = idx / h, ox = idx - oy * h;
        float4 q = make_float4(sv[oy * S + ox], sv[oy * S + ox + 1],
                               sv[(oy + 1) * S + ox], sv[(oy + 1) * S + ox + 1]);
        g_q[co2[i] + b * h * h + idx] = q;
    }
}

// ---- k_tail: per-channel L2->chain (blocks 0..23) + comb strips i=0 (24..151) --
__global__ void __launch_bounds__(1024) k_tail() {
    extern __shared__ float sm[];
    __shared__ float scs[3];
    __shared__ unsigned s1mn, s1mx, s1tile[64];
    __shared__ unsigned t_mn[5], t_mx[5], t_tile[17];
    const int t = threadIdx.x, B = blockIdx.x;
    if (B >= 24) { comb_strip(t, B - 24, sm, scs); return; }

    const int bc = B;
    float* F = sm;           // 16384 (L2, then diff1 in place)
    float* H = sm + 16384;   // 8192
    float* C = sm + 24576;   // 4096 (L3)
    if (t == 0) { s1mn = 0xFFFFFFFFu; s1mx = 0u; }
    if (t < 64) s1tile[t] = 0u;
    if (t < 5) { t_mn[t] = 0xFFFFFFFFu; t_mx[t] = 0u; }
    if (t < 17) t_tile[t] = 0u;
    // load L2 map
    {
        const float4* src = (const float4*)(g_pyr + 1572864 + (size_t)bc * 16384);
        float4* F4 = (float4*)F;
        for (int idx = t; idx < 4096; idx += 1024) F4[idx] = src[idx];
    }
    __syncthreads();
    // H-pass: 128 rows x 64 cols
    for (int idx = t; idx < 8192; idx += 1024) {
        int r = idx >> 6;
        const float* row = F + (r << 7);
        int c0 = 2 * (idx & 63);
        H[idx] = W0 * (row[refl(c0 - 2, 128)] + row[refl(c0 + 3, 128)])
               + W1 * (row[refl(c0 - 1, 128)] + row[refl(c0 + 2, 128)])
               + W2 * (row[c0] + row[c0 + 1]);
    }
    __syncthreads();
    // V-pass -> L3 (C) + diff1 + stats
    {
        float lmn = CUDART_INF_F, lmx = -CUDART_INF_F;
        float* gd1 = g_d + 1572864 + (size_t)bc * 16384;
        for (int idx = t; idx < 4096; idx += 1024) {
            int oy = idx >> 6, ox = idx & 63;
            int r0 = 2 * oy;
            float cv = W0 * (H[(refl(r0 - 2, 128) << 6) + ox] +
                             H[(refl(r0 + 3, 128) << 6) + ox])
                     + W1 * (H[(refl(r0 - 1, 128) << 6) + ox] +
                             H[(refl(r0 + 2, 128) << 6) + ox])
                     + W2 * (H[(r0 << 6) + ox] + H[((r0 + 1) << 6) + ox]);
            C[idx] = cv;
            int f0 = (oy << 8) + 2 * ox;
            float d00 = fabsf(F[f0] - cv),       d01 = fabsf(F[f0 + 1] - cv);
            float d10 = fabsf(F[f0 + 128] - cv), d11 = fabsf(F[f0 + 129] - cv);
            *(float2*)(gd1 + f0) = make_float2(d00, d01);
            *(float2*)(gd1 + f0 + 128) = make_float2(d10, d11);
            float mx4 = fmaxf(fmaxf(d00, d01), fmaxf(d10, d11));
            float mn4 = fminf(fminf(d00, d01), fminf(d10, d11));
            atomicMax(&s1tile[(oy >> 3) * 8 + (ox >> 3)], __float_as_uint(mx4));
            lmx = fmaxf(lmx, mx4);
            lmn = fminf(lmn, mn4);
        }
        for (int o = 16; o; o >>= 1) {
            lmx = fmaxf(lmx, __shfl_xor_sync(~0u, lmx, o));
            lmn = fminf(lmn, __shfl_xor_sync(~0u, lmn, o));
        }
        if ((t & 31) == 0) {
            atomicMax(&s1mx, __float_as_uint(lmx));
            atomicMin(&s1mn, __float_as_uint(lmn));
        }
    }
    __syncthreads();
    if (t == 0) {
        float ts = 0.f;
        for (int k = 0; k < 64; k++) {
            int ty = k >> 3, tx = k & 7;
            if (tx < 7 && ty < 7) ts += __uint_as_float(s1tile[k]);
        }
        const int sidx = bc * 7 + 1;
        g_dmn[sidx] = s1mn;
        g_dmx[sidx] = s1mx;
        g_tsum[sidx] = ts;
    }
    __syncthreads();
    // chain i=2..6 from L3 (C); ping-pong inside the free F region
    float* A0 = C;          // 4096 (input, diffs in place)
    float* A1 = F;          // outputs (<=1024)
    float* HH = F + 8192;   // H scratch (<=2048)
    tail_stage2<6>(t, bc, A0, A1, HH, t_mn, t_mx, t_tile);
    tail_stage2<5>(t, bc, A1, A0, HH, t_mn, t_mx, t_tile);
    tail_stage2<4>(t, bc, A0, A1, HH, t_mn, t_mx, t_tile);
    tail_stage2<3>(t, bc, A1, A0, HH, t_mn, t_mx, t_tile);
    tail_stage2<2>(t, bc, A0, A1, HH, t_mn, t_mx, t_tile);
    if (t < 5) {
        const int s = t, I = s + 2, sidx = bc * 7 + I;
        float ts = 0.f;
        if (s == 0) {
            for (int k = 0; k < 3; k++)
                for (int j = 0; j < 3; j++) ts += __uint_as_float(t_tile[k * 4 + j]);
        } else if (s == 1) ts = __uint_as_float(t_tile[16]);
        g_dmn[sidx] = t_mn[s];
        g_dmx[sidx] = t_mx[s];
        g_tsum[sidx] = ts;
    }
}

// ---- k_comb: strips i=1 (blocks 0..63) + comb_small (64..103) ------------------
__global__ void __launch_bounds__(1024) k_comb() {
    extern __shared__ float sm[];
    __shared__ float scs[3];
    const int t = threadIdx.x, B = blockIdx.x;
    if (B < 64) comb_strip(t, 128 + B, sm, scs);
    else comb_small(t, B - 64, sm, scs);
}

// ---- fused final gather: 2 rows per block (unchanged, proven) ------------------
__global__ void __launch_bounds__(1024) k_final(float* __restrict__ out) {
    __shared__ int sr0[2][7];
    __shared__ float swy[2][7], sob;
    const int t = threadIdx.x;
    const int b = blockIdx.x >> 8;
    const int yp = blockIdx.x & 255;
    if (t < 32) {
        float v = 0.f;
        if (t < 21) {
            int c = t / 7, ii = t - c * 7;
            float mn;
            float sc = calc_scale((b * 3 + c) * 7 + ii, ii, &mn);
            v = -mn * sc;
        }
        for (int o = 16; o; o >>= 1) v += __shfl_xor_sync(~0u, v, o);
        if (t == 0) sob = v;
    }
    if (t >= 64 && t < 78) {
        int k = t - 64;
        int r = k / 7, ii = k - r * 7;
        int hh = 256 >> ii;
        int yy = 2 * yp + r;
        float fy = fminf(fmaxf((yy + 0.5f) * (float)hh * (1.f / 512.f) - 0.5f, 0.f),
                         (float)(hh - 1));
        int y0 = (int)fy;
        swy[r][ii] = fy - (float)y0;
        sr0[r][ii] = y0 * hh;
    }
    __syncthreads();
    const int r = t >> 9;
    const int x = t & 511;
    const int y = 2 * yp + r;
    float acc = 0.f;
#pragma unroll
    for (int i = 0; i < 7; i++) {
        const int hh = 256 >> i;
        float fx = fminf(fmaxf((x + 0.5f) * (float)hh * (1.f / 512.f) - 0.5f, 0.f),
                         (float)(hh - 1));
        int x0 = (int)fx;
        float wx = fx - (float)x0;
        float4 p = g_q[co2[i] + (size_t)b * hh * hh + sr0[r][i] + x0];
        float v0 = fmaf(wx, p.y - p.x, p.x);
        float v1 = fmaf(wx, p.w - p.z, p.z);
        acc += fmaf(swy[r][i], v1 - v0, v0);
    }
    out[((size_t)b << 18) + y * 512 + x] = acc + sob;
}

extern "C" void kernel_launch(void* const* d_in, const int* in_sizes, int n_in,
                              void* d_out, int out_size) {
    const float* x = (const float*)d_in[0];
    float* out = (float*)d_out;

    cudaFuncSetAttribute(k_tail, cudaFuncAttributeMaxDynamicSharedMemorySize, 114688);

    k_pyr0<<<dim3(8, 16, 24), 512>>>(x);   // 512 -> 256 (+ stat init)
    k_pd1<<<dim3(4, 8, 24), 512>>>();      // 256 -> 128 + diff0 + stats
    k_tail<<<152, 1024, 114688>>>();       // L2->L3+diff1 + chain i=2..6 | strips i=0
    k_comb<<<104, 1024, 17544>>>();        // strips i=1 + comb_small i=2..6
    k_final<<<2048, 1024>>>(out);
}

// round 12
// speedup vs baseline: 1.1988x; 1.0578x over previous
#include <cuda_runtime.h>
#include <cuda_device_runtime_api.h>
#include <math_constants.h>

// ---------------------------------------------------------------------------
// IttiKochSaliency, x[8,3,512,512] -> out[8,512,512]
//
// 5 launches chained with PDL (programmatic dependent launch): each dependent
// kernel is launched with ProgrammaticStreamSerialization and performs
// cudaGridDependencySynchronize() before consuming predecessor data, hiding
// the inter-launch gap (~20us of the R11 wall) behind predecessor execution.
//
//  k_pyr0 : x -> L1 (256^2), separable 6-tap stride-2 reflect (+ stat init)
//  k_pd1  : L1 -> L2 + diff0 + stats (768 tiles)
//  k_tail : blocks 0..23 -> per-(b,c): L2 (smem) -> L3 (smem), diff1 + stats,
//           chain i=2..6 (diffs -> g_d2, stats); blocks 24..151 -> comb i=0
//  k_comb : comb strips i=1 (64) + comb_small i=2..6 (40)
//  k_final: 7-level bilinear gather, 1 LDG.128 per level per pixel
// ---------------------------------------------------------------------------

__device__ float    g_pyr[1966080];   // L1 @0 (256^2/bc), L2 @1572864 (128^2/bc)
__device__ float    g_d[1966080];     // diff0 @0, diff1 @1572864
__device__ float    g_d2[130944];     // diffs i=2..6 per bc (5456 each)
__device__ float4   g_q[699008];      // quad-dup combined maps per (b,i)
__device__ unsigned g_dmn[168], g_dmx[168];
__device__ float    g_tsum[168];

__constant__ int co2[7]   = {0, 524288, 655360, 688128, 696320, 698368, 698880};
__constant__ int d2off[5] = {0, 4096, 5120, 5376, 5440};

#if defined(__CUDA_ARCH__) && __CUDA_ARCH__ >= 900
#define GRID_DEP_SYNC() cudaGridDependencySynchronize()
#else
#define GRID_DEP_SYNC()
#endif

__device__ __forceinline__ int refl(int t, int n) {
    return t < 0 ? -t : (t >= n ? 2 * n - 2 - t : t);
}
__device__ __forceinline__ float calc_scale(int sidx, int i, float* mn_out) {
    float mn = __uint_as_float(g_dmn[sidx]);
    float mx = __uint_as_float(g_dmx[sidx]);
    float inv = 1.f / (mx - mn);
    int n = (16 >> i) - 1;
    float lm = (n > 0) ? (g_tsum[sidx] / (float)(n * n) - mn) * inv : 0.f;
    float om = 1.f - lm;
    *mn_out = mn;
    return om * om * inv * (1.f / 3.f);
}

#define W0 0.03125f
#define W1 0.15625f
#define W2 0.3125f

// ---------------- level 0 pyrdown: 512 -> 256 --------------------------------
__global__ void __launch_bounds__(512) k_pyr0(const float* __restrict__ x) {
    constexpr int HI = 512, HO = 256;
    __shared__ float s_in[36 * 68];
    __shared__ float s_h[36 * 32];
    const int t = threadIdx.x;
    if (blockIdx.x == 0 && blockIdx.y == 0 && blockIdx.z == 0 && t < 168) {
        g_dmn[t] = 0xFFFFFFFFu; g_dmx[t] = 0u; g_tsum[t] = 0.f;
    }
    const int bc = blockIdx.z;
    const int ox0 = blockIdx.x * 32, oy0 = blockIdx.y * 16;
    const float* in = x + (size_t)bc * HI * HI;
    float* out = g_pyr + (size_t)bc * HO * HO;
    const int iy0 = 2 * oy0 - 2, ix0 = 2 * ox0 - 2;
    for (int idx = t; idx < 36 * 34; idx += 512) {
        int r = idx / 34, c2 = idx - r * 34;
        int gy = refl(iy0 + r, HI);
        int ix = ix0 + 2 * c2;
        float v0, v1;
        if (ix >= 0 && ix + 2 <= HI) {
            float2 p = *(const float2*)(in + gy * HI + ix);
            v0 = p.x; v1 = p.y;
        } else {
            v0 = in[gy * HI + refl(ix, HI)];
            v1 = in[gy * HI + refl(ix + 1, HI)];
        }
        s_in[r * 68 + 2 * c2] = v0;
        s_in[r * 68 + 2 * c2 + 1] = v1;
    }
    __syncthreads();
    for (int idx = t; idx < 36 * 32; idx += 512) {
        int r = idx >> 5, c = idx & 31;
        const float* p = s_in + r * 68 + 2 * c;
        s_h[idx] = W0 * (p[0] + p[5]) + W1 * (p[1] + p[4]) + W2 * (p[2] + p[3]);
    }
    __syncthreads();
    const int tx = t & 31, ty = t >> 5;
    const float* q = s_h + 2 * ty * 32 + tx;
    float acc = W0 * (q[0] + q[160]) + W1 * (q[32] + q[128]) + W2 * (q[64] + q[96]);
    out[(oy0 + ty) * HO + ox0 + tx] = acc;
}

// ---------------- pyrdown + fused diff0 ---------------------------------------
__global__ void __launch_bounds__(512) k_pd1() {
    constexpr int HI = 256;
    constexpr int NT = 15;
    __shared__ float s_in[36 * 68];
    __shared__ float s_h[36 * 32];
    __shared__ float sout[16 * 32];
    __shared__ unsigned s_mn, s_mx, stile[8];
    const int t = threadIdx.x;
    if (t == 0) { s_mn = 0xFFFFFFFFu; s_mx = 0u; }
    if (t < 8) stile[t] = 0u;
    GRID_DEP_SYNC();
    const int bc = blockIdx.z;
    const int ox0 = blockIdx.x * 32, oy0 = blockIdx.y * 16;
    const float* in = g_pyr + (size_t)bc * HI * HI;
    float* outp = g_pyr + 1572864 + (size_t)bc * 16384;
    const int iy0 = 2 * oy0 - 2, ix0 = 2 * ox0 - 2;
    for (int idx = t; idx < 36 * 34; idx += 512) {
        int r = idx / 34, c2 = idx - r * 34;
        int gy = refl(iy0 + r, HI);
        int ix = ix0 + 2 * c2;
        float v0, v1;
        if (ix >= 0 && ix + 2 <= HI) {
            float2 p = *(const float2*)(in + gy * HI + ix);
            v0 = p.x; v1 = p.y;
        } else {
            v0 = in[gy * HI + refl(ix, HI)];
            v1 = in[gy * HI + refl(ix + 1, HI)];
        }
        s_in[r * 68 + 2 * c2] = v0;
        s_in[r * 68 + 2 * c2 + 1] = v1;
    }
    __syncthreads();
    for (int idx = t; idx < 36 * 32; idx += 512) {
        int r = idx >> 5, c = idx & 31;
        const float* p = s_in + r * 68 + 2 * c;
        s_h[idx] = W0 * (p[0] + p[5]) + W1 * (p[1] + p[4]) + W2 * (p[2] + p[3]);
    }
    __syncthreads();
    {
        const int tx = t & 31, ty = t >> 5;
        const float* q = s_h + 2 * ty * 32 + tx;
        float acc = W0 * (q[0] + q[160]) + W1 * (q[32] + q[128]) + W2 * (q[64] + q[96]);
        outp[(oy0 + ty) * 128 + ox0 + tx] = acc;
        sout[ty * 32 + tx] = acc;
    }
    __syncthreads();
    {
        const int p = t * 4;
        const int ly = p >> 6, lx = p & 63;
        const float* fr = s_in + (ly + 2) * 68 + lx + 2;
        const float c0 = sout[(ly >> 1) * 32 + (lx >> 1)];
        const float c1 = sout[(ly >> 1) * 32 + (lx >> 1) + 1];
        float d0 = fabsf(fr[0] - c0), d1 = fabsf(fr[1] - c0);
        float d2 = fabsf(fr[2] - c1), d3 = fabsf(fr[3] - c1);
        float* gd = g_d + (size_t)bc * 65536;
        *(float4*)(gd + (2 * oy0 + ly) * 256 + 2 * ox0 + lx) = make_float4(d0, d1, d2, d3);
        float mx4 = fmaxf(fmaxf(d0, d1), fmaxf(d2, d3));
        float mn4 = fminf(fminf(d0, d1), fminf(d2, d3));
        float tm = mx4;
        tm = fmaxf(tm, __shfl_xor_sync(~0u, tm, 1, 4));
        tm = fmaxf(tm, __shfl_xor_sync(~0u, tm, 2, 4));
        if ((t & 3) == 0)
            atomicMax(&stile[(ly >> 4) * 4 + (lx >> 4)], __float_as_uint(tm));
        for (int o = 16; o; o >>= 1) {
            mx4 = fmaxf(mx4, __shfl_xor_sync(~0u, mx4, o));
            mn4 = fminf(mn4, __shfl_xor_sync(~0u, mn4, o));
        }
        if ((t & 31) == 0) {
            atomicMax(&s_mx, __float_as_uint(mx4));
            atomicMin(&s_mn, __float_as_uint(mn4));
        }
    }
    __syncthreads();
    const int sidx = bc * 7;
    if (t == 0) { atomicMin(&g_dmn[sidx], s_mn); atomicMax(&g_dmx[sidx], s_mx); }
    if (t < 8) {
        int gtc = 4 * blockIdx.x + (t & 3);
        int gtr = 2 * blockIdx.y + (t >> 2);
        if (gtc < NT && gtr < NT)
            atomicAdd(&g_tsum[sidx], __uint_as_float(stile[t]));
    }
}

// ---- per-channel tail stage (proven, 1024-thread stride) ---------------------
template <int LGF>
__device__ __forceinline__ void tail_stage2(int t, int bc, float* F, float* C,
                                            float* H, unsigned* t_mn,
                                            unsigned* t_mx, unsigned* t_tile) {
    constexpr int HF = 1 << LGF, HC = HF >> 1;
    constexpr int S = 6 - LGF;
    constexpr int OFF = (LGF == 6) ? 0 : (LGF == 5) ? 4096 :
                        (LGF == 4) ? 5120 : (LGF == 3) ? 5376 : 5440;
    for (int idx = t; idx < HF * HC; idx += 1024) {
        int r = idx >> (LGF - 1);
        const float* row = F + (r << LGF);
        int c0 = 2 * (idx & (HC - 1));
        H[idx] = W0 * (row[refl(c0 - 2, HF)] + row[refl(c0 + 3, HF)])
               + W1 * (row[refl(c0 - 1, HF)] + row[refl(c0 + 2, HF)])
               + W2 * (row[c0] + row[c0 + 1]);
    }
    __syncthreads();
    float* gd2 = g_d2 + bc * 5456 + OFF;
    for (int idx = t; idx < HC * HC; idx += 1024) {
        int oy = idx >> (LGF - 1), ox = idx & (HC - 1);
        int r0 = 2 * oy;
        float cv = W0 * (H[(refl(r0 - 2, HF) << (LGF - 1)) + ox] +
                         H[(refl(r0 + 3, HF) << (LGF - 1)) + ox])
                 + W1 * (H[(refl(r0 - 1, HF) << (LGF - 1)) + ox] +
                         H[(refl(r0 + 2, HF) << (LGF - 1)) + ox])
                 + W2 * (H[(r0 << (LGF - 1)) + ox] + H[((r0 + 1) << (LGF - 1)) + ox]);
        C[idx] = cv;
        int f0 = (oy << (LGF + 1)) + 2 * ox;
        float d00 = fabsf(F[f0] - cv),      d01 = fabsf(F[f0 + 1] - cv);
        float d10 = fabsf(F[f0 + HF] - cv), d11 = fabsf(F[f0 + HF + 1] - cv);
        F[f0] = d00; F[f0 + 1] = d01; F[f0 + HF] = d10; F[f0 + HF + 1] = d11;
        *(float2*)(gd2 + f0) = make_float2(d00, d01);
        *(float2*)(gd2 + f0 + HF) = make_float2(d10, d11);
        float mx4 = fmaxf(fmaxf(d00, d01), fmaxf(d10, d11));
        float mn4 = fminf(fminf(d00, d01), fminf(d10, d11));
        if (LGF >= 4) {
            float a = mx4, n2 = mn4;
            for (int o = 16; o; o >>= 1) {
                a = fmaxf(a, __shfl_xor_sync(~0u, a, o));
                n2 = fminf(n2, __shfl_xor_sync(~0u, n2, o));
            }
            if ((t & 31) == 0) {
                atomicMax(&t_mx[S], __float_as_uint(a));
                atomicMin(&t_mn[S], __float_as_uint(n2));
            }
        } else {
            atomicMax(&t_mx[S], __float_as_uint(mx4));
            atomicMin(&t_mn[S], __float_as_uint(mn4));
        }
        if (LGF == 6)
            atomicMax(&t_tile[(oy >> 3) * 4 + (ox >> 3)], __float_as_uint(mx4));
        else if (LGF == 5) {
            if (oy < 8 && ox < 8) atomicMax(&t_tile[16], __float_as_uint(mx4));
        }
    }
    __syncthreads();
}

// ---- comb strip (full-width 16-row strip for i=0,1), stride 1024 -------------
__device__ __forceinline__ void comb_strip(int t, int k, float* sm, float* scs) {
    int i, b, y0, lg;
    if (k < 128) { i = 0; b = k >> 4; y0 = (k & 15) * 16; lg = 8; }
    else { int r = k - 128; i = 1; b = r >> 3; y0 = (r & 7) * 16; lg = 7; }
    const int h = 1 << lg, S = h + 2, W = h + 1;
    float* sv = sm;
    if (t < 3) { float mn; scs[t] = calc_scale((b * 3 + t) * 7 + i, i, &mn); }
    __syncthreads();
    const float* db = g_d + (i ? 1572864 : 0) + (size_t)(b * 3) * h * h;
    for (int idx = t; idx < 17 * W; idx += 1024) {
        int yy = idx / W, xx = idx - yy * W;
        int gx = min(xx, h - 1), gy = min(y0 + yy, h - 1);
        const float* p = db + gy * h + gx;
        sv[yy * S + xx] = scs[0] * p[0] + scs[1] * p[h * h] + scs[2] * p[2 * h * h];
    }
    __syncthreads();
    for (int idx = t; idx < (h << 4); idx += 1024) {
        int oy = idx >> lg, ox = idx & (h - 1);
        float4 q = make_float4(sv[oy * S + ox], sv[oy * S + ox + 1],
                               sv[(oy + 1) * S + ox], sv[(oy + 1) * S + ox + 1]);
        g_q[co2[i] + b * h * h + (y0 + oy) * h + ox] = q;
    }
}

// ---- comb for one (b, i>=2) level, stride 1024 --------------------------------
__device__ __forceinline__ void comb_small(int t, int k, float* sm, float* scs) {
    const int b = k / 5, i2 = k - b * 5, i = 2 + i2;
    const int h = 64 >> i2, hp = h + 1, S = h + 2;
    float* sv = sm;
    if (t < 3) { float mn; scs[t] = calc_scale((b * 3 + t) * 7 + i, i, &mn); }
    __syncthreads();
    const float* db = g_d2 + d2off[i2];
    for (int idx = t; idx < hp * hp; idx += 1024) {
        int yy = idx / hp, xx = idx - yy * hp;
        int gx = min(xx, h - 1), gy = min(yy, h - 1);
        int p = gy * h + gx;
        sv[yy * S + xx] = scs[0] * db[(b * 3) * 5456 + p]
                        + scs[1] * db[(b * 3 + 1) * 5456 + p]
                        + scs[2] * db[(b * 3 + 2) * 5456 + p];
    }
    __syncthreads();
    for (int idx = t; idx < h * h; idx += 1024) {
        int oy = idx / h, ox = idx - oy * h;
        float4 q = make_float4(sv[oy * S + ox], sv[oy * S + ox + 1],
                               sv[(oy + 1) * S + ox], sv[(oy + 1) * S + ox + 1]);
        g_q[co2[i] + b * h * h + idx] = q;
    }
}

// ---- k_tail: per-channel L2->chain (blocks 0..23) + comb strips i=0 (24..151) --
__global__ void __launch_bounds__(1024) k_tail() {
    extern __shared__ float sm[];
    __shared__ float scs[3];
    __shared__ unsigned s1mn, s1mx, s1tile[64];
    __shared__ unsigned t_mn[5], t_mx[5], t_tile[17];
    const int t = threadIdx.x, B = blockIdx.x;
    GRID_DEP_SYNC();
    if (B >= 24) { comb_strip(t, B - 24, sm, scs); return; }

    const int bc = B;
    float* F = sm;           // 16384 (L2, then diff1 in place)
    float* H = sm + 16384;   // 8192
    float* C = sm + 24576;   // 4096 (L3)
    if (t == 0) { s1mn = 0xFFFFFFFFu; s1mx = 0u; }
    if (t < 64) s1tile[t] = 0u;
    if (t < 5) { t_mn[t] = 0xFFFFFFFFu; t_mx[t] = 0u; }
    if (t < 17) t_tile[t] = 0u;
    {
        const float4* src = (const float4*)(g_pyr + 1572864 + (size_t)bc * 16384);
        float4* F4 = (float4*)F;
        for (int idx = t; idx < 4096; idx += 1024) F4[idx] = src[idx];
    }
    __syncthreads();
    for (int idx = t; idx < 8192; idx += 1024) {
        int r = idx >> 6;
        const float* row = F + (r << 7);
        int c0 = 2 * (idx & 63);
        H[idx] = W0 * (row[refl(c0 - 2, 128)] + row[refl(c0 + 3, 128)])
               + W1 * (row[refl(c0 - 1, 128)] + row[refl(c0 + 2, 128)])
               + W2 * (row[c0] + row[c0 + 1]);
    }
    __syncthreads();
    {
        float lmn = CUDART_INF_F, lmx = -CUDART_INF_F;
        float* gd1 = g_d + 1572864 + (size_t)bc * 16384;
        for (int idx = t; idx < 4096; idx += 1024) {
            int oy = idx >> 6, ox = idx & 63;
            int r0 = 2 * oy;
            float cv = W0 * (H[(refl(r0 - 2, 128) << 6) + ox] +
                             H[(refl(r0 + 3, 128) << 6) + ox])
                     + W1 * (H[(refl(r0 - 1, 128) << 6) + ox] +
                             H[(refl(r0 + 2, 128) << 6) + ox])
                     + W2 * (H[(r0 << 6) + ox] + H[((r0 + 1) << 6) + ox]);
            C[idx] = cv;
            int f0 = (oy << 8) + 2 * ox;
            float d00 = fabsf(F[f0] - cv),       d01 = fabsf(F[f0 + 1] - cv);
            float d10 = fabsf(F[f0 + 128] - cv), d11 = fabsf(F[f0 + 129] - cv);
            *(float2*)(gd1 + f0) = make_float2(d00, d01);
            *(float2*)(gd1 + f0 + 128) = make_float2(d10, d11);
            float mx4 = fmaxf(fmaxf(d00, d01), fmaxf(d10, d11));
            float mn4 = fminf(fminf(d00, d01), fminf(d10, d11));
            atomicMax(&s1tile[(oy >> 3) * 8 + (ox >> 3)], __float_as_uint(mx4));
            lmx = fmaxf(lmx, mx4);
            lmn = fminf(lmn, mn4);
        }
        for (int o = 16; o; o >>= 1) {
            lmx = fmaxf(lmx, __shfl_xor_sync(~0u, lmx, o));
            lmn = fminf(lmn, __shfl_xor_sync(~0u, lmn, o));
        }
        if ((t & 31) == 0) {
            atomicMax(&s1mx, __float_as_uint(lmx));
            atomicMin(&s1mn, __float_as_uint(lmn));
        }
    }
    __syncthreads();
    if (t == 0) {
        float ts = 0.f;
        for (int k = 0; k < 64; k++) {
            int ty = k >> 3, tx = k & 7;
            if (tx < 7 && ty < 7) ts += __uint_as_float(s1tile[k]);
        }
        const int sidx = bc * 7 + 1;
        g_dmn[sidx] = s1mn;
        g_dmx[sidx] = s1mx;
        g_tsum[sidx] = ts;
    }
    __syncthreads();
    float* A0 = C;
    float* A1 = F;
    float* HH = F + 8192;
    tail_stage2<6>(t, bc, A0, A1, HH, t_mn, t_mx, t_tile);
    tail_stage2<5>(t, bc, A1, A0, HH, t_mn, t_mx, t_tile);
    tail_stage2<4>(t, bc, A0, A1, HH, t_mn, t_mx, t_tile);
    tail_stage2<3>(t, bc, A1, A0, HH, t_mn, t_mx, t_tile);
    tail_stage2<2>(t, bc, A0, A1, HH, t_mn, t_mx, t_tile);
    if (t < 5) {
        const int s = t, I = s + 2, sidx = bc * 7 + I;
        float ts = 0.f;
        if (s == 0) {
            for (int k = 0; k < 3; k++)
                for (int j = 0; j < 3; j++) ts += __uint_as_float(t_tile[k * 4 + j]);
        } else if (s == 1) ts = __uint_as_float(t_tile[16]);
        g_dmn[sidx] = t_mn[s];
        g_dmx[sidx] = t_mx[s];
        g_tsum[sidx] = ts;
    }
}

// ---- k_comb: strips i=1 (blocks 0..63) + comb_small (64..103) ------------------
__global__ void __launch_bounds__(1024) k_comb() {
    extern __shared__ float sm[];
    __shared__ float scs[3];
    const int t = threadIdx.x, B = blockIdx.x;
    GRID_DEP_SYNC();
    if (B < 64) comb_strip(t, 128 + B, sm, scs);
    else comb_small(t, B - 64, sm, scs);
}

// ---- fused final gather: 2 rows per block ---------------------------------------
__global__ void __launch_bounds__(1024) k_final(float* __restrict__ out) {
    __shared__ int sr0[2][7];
    __shared__ float swy[2][7], sob;
    const int t = threadIdx.x;
    const int b = blockIdx.x >> 8;
    const int yp = blockIdx.x & 255;
    GRID_DEP_SYNC();
    if (t < 32) {
        float v = 0.f;
        if (t < 21) {
            int c = t / 7, ii = t - c * 7;
            float mn;
            float sc = calc_scale((b * 3 + c) * 7 + ii, ii, &mn);
            v = -mn * sc;
        }
        for (int o = 16; o; o >>= 1) v += __shfl_xor_sync(~0u, v, o);
        if (t == 0) sob = v;
    }
    if (t >= 64 && t < 78) {
        int k = t - 64;
        int r = k / 7, ii = k - r * 7;
        int hh = 256 >> ii;
        int yy = 2 * yp + r;
        float fy = fminf(fmaxf((yy + 0.5f) * (float)hh * (1.f / 512.f) - 0.5f, 0.f),
                         (float)(hh - 1));
        int y0 = (int)fy;
        swy[r][ii] = fy - (float)y0;
        sr0[r][ii] = y0 * hh;
    }
    __syncthreads();
    const int r = t >> 9;
    const int x = t & 511;
    const int y = 2 * yp + r;
    float acc = 0.f;
#pragma unroll
    for (int i = 0; i < 7; i++) {
        const int hh = 256 >> i;
        float fx = fminf(fmaxf((x + 0.5f) * (float)hh * (1.f / 512.f) - 0.5f, 0.f),
                         (float)(hh - 1));
        int x0 = (int)fx;
        float wx = fx - (float)x0;
        float4 p = g_q[co2[i] + (size_t)b * hh * hh + sr0[r][i] + x0];
        float v0 = fmaf(wx, p.y - p.x, p.x);
        float v1 = fmaf(wx, p.w - p.z, p.z);
        acc += fmaf(swy[r][i], v1 - v0, v0);
    }
    out[((size_t)b << 18) + y * 512 + x] = acc + sob;
}

// ---- host: PDL launcher with plain-launch fallback ------------------------------
static void pdl_launch(const void* fn, dim3 grid, dim3 block, size_t smem,
                       void** args) {
    cudaLaunchConfig_t cfg = {};
    cfg.gridDim = grid;
    cfg.blockDim = block;
    cfg.dynamicSmemBytes = smem;
    cfg.stream = 0;
    cudaLaunchAttribute at[1];
    at[0].id = cudaLaunchAttributeProgrammaticStreamSerialization;
    at[0].val.programmaticStreamSerializationAllowed = 1;
    cfg.attrs = at;
    cfg.numAttrs = 1;
    if (cudaLaunchKernelExC(&cfg, fn, args) != cudaSuccess) {
        cudaLaunchKernel(fn, grid, block, args, smem, 0);
    }
}

extern "C" void kernel_launch(void* const* d_in, const int* in_sizes, int n_in,
                              void* d_out, int out_size) {
    const float* x = (const float*)d_in[0];
    float* out = (float*)d_out;

    cudaFuncSetAttribute(k_tail, cudaFuncAttributeMaxDynamicSharedMemorySize, 114688);

    k_pyr0<<<dim3(8, 16, 24), 512>>>(x);
    pdl_launch((const void*)k_pd1, dim3(4, 8, 24), dim3(512), 0, nullptr);
    pdl_launch((const void*)k_tail, dim3(152), dim3(1024), 114688, nullptr);
    pdl_launch((const void*)k_comb, dim3(104), dim3(1024), 17544, nullptr);
    void* fargs[] = {&out};
    pdl_launch((const void*)k_final, dim3(2048), dim3(1024), 0, fargs);
}